// round 7
// baseline (speedup 1.0000x reference)
#include <cuda_runtime.h>

typedef unsigned long long ull;

#define TT       30
#define BB       1048576
#define THREADS  128
#define M        4
#define QUARTER  (BB / 4)

// Small weights in constant (LDC port); W1 in shared (LDS port).
__constant__ __align__(16) float cB1[TT * 20];      // 600 floats
__constant__ __align__(16) float cW2[TT * 20];      // 600
__constant__ __align__(16) float cB2[TT];           // 30

// ---------------- packed f32x2 helpers ----------------
__device__ __forceinline__ ull pk(float lo, float hi) {
    ull r; asm("mov.b64 %0, {%1,%2};" : "=l"(r) : "f"(lo), "f"(hi)); return r;
}
__device__ __forceinline__ void upk(float& lo, float& hi, ull v) {
    asm("mov.b64 {%0,%1}, %2;" : "=f"(lo), "=f"(hi) : "l"(v));
}
__device__ __forceinline__ ull fma2(ull a, ull b, ull c) {
    ull d; asm("fma.rn.f32x2 %0, %1, %2, %3;" : "=l"(d) : "l"(a), "l"(b), "l"(c)); return d;
}
__device__ __forceinline__ ull add2(ull a, ull b) {
    ull d; asm("add.rn.f32x2 %0, %1, %2;" : "=l"(d) : "l"(a), "l"(b)); return d;
}
__device__ __forceinline__ ull relu2(ull v) {
    float a, b; upk(a, b, v);
    return pk(fmaxf(a, 0.0f), fmaxf(b, 0.0f));
}
// tanh(z) = 1 - 2/(exp(2z)+1) via MUFU.EX2 + MUFU.RCP (~1e-6 rel err)
__device__ __forceinline__ float fast_tanh(float z) {
    float e; asm("ex2.approx.f32 %0, %1;" : "=f"(e) : "f"(z * 2.8853900817779268f));
    float r; asm("rcp.approx.f32 %0, %1;" : "=f"(r) : "f"(e + 1.0f));
    return fmaf(-2.0f, r, 1.0f);
}

// Shared layout (floats):
//   sW1 : [0, 1200)       W1 [T][2][20]
//   sIO : [1200, 16560)   x/out staging: M regions x 128 elems x 30 floats
#define REGF        (THREADS * TT)              // 3840 floats per region
#define SMEM_FLOATS (1200 + M * REGF)           // 16560 floats = 66240 bytes

__global__ __launch_bounds__(THREADS, 3)
void rnn_kernel(const float* __restrict__ gx,
                const float* __restrict__ gW1,
                float* __restrict__ gout)
{
    extern __shared__ float smem[];
    float* sW1 = smem;
    float* sIO = smem + 1200;

    const int tid = threadIdx.x;
    const int ebase = blockIdx.x * THREADS;   // region-0 element base

    // ---- stage W1 (coalesced float4) ----
    {
        float4*       d = (float4*)sW1;
        const float4* s = (const float4*)gW1;
        for (int i = tid; i < 300; i += THREADS) d[i] = s[i];
    }
    // ---- stage x: M regions, each 960 float4, coalesced ----
    {
        float4* d = (float4*)sIO;
        #pragma unroll
        for (int r = 0; r < M; ++r) {
            const float4* s = (const float4*)(gx + (size_t)(ebase + r * QUARTER) * TT);
            for (int i = tid; i < REGF / 4; i += THREADS) d[r * (REGF / 4) + i] = s[i];
        }
    }
    __syncthreads();

    // This thread's 4 elements
    float* io[M];
    #pragma unroll
    for (int r = 0; r < M; ++r) io[r] = sIO + r * REGF + tid * TT;

    const ulonglong2* w1p = (const ulonglong2*)sW1;          // 10 ulonglong2 per t
    const ull*        b1u = (const ull*)cB1;                 // per t: 10 ulls
    const ull*        w2u = (const ull*)cW2;                 // per t: 10 ulls

    float o[M];
    #pragma unroll
    for (int m = 0; m < M; ++m) o[m] = 0.0f;

    // ---- software-pipelined weight/x prefetch (double buffer) ----
    ulonglong2 wbuf[2][10];
    float      xbuf[2][M];

    #pragma unroll
    for (int q = 0; q < 10; ++q) wbuf[0][q] = w1p[q];
    #pragma unroll
    for (int m = 0; m < M; ++m)  xbuf[0][m] = io[m][0];

    #pragma unroll 2
    for (int t = 0; t < TT; ++t) {
        const int cur = t & 1;
        const int nxt = cur ^ 1;
        const int tn  = (t < TT - 1) ? t + 1 : t;   // clamp (last prefetch harmless)

        // Issue next timestep's long-latency loads NOW, consume later.
        const ulonglong2* w1n = w1p + tn * 10;
        #pragma unroll
        for (int q = 0; q < 10; ++q) wbuf[nxt][q] = w1n[q];
        #pragma unroll
        for (int m = 0; m < M; ++m)  xbuf[nxt][m] = io[m][tn];

        const ulonglong2* b1t = (const ulonglong2*)(b1u + t * 10);  // LDC.128
        const ulonglong2* w2t = (const ulonglong2*)(w2u + t * 10);  // LDC.128
        const float bt2 = cB2[t];

        ull xx[M], oo[M], accA[M], accB[M];
        #pragma unroll
        for (int m = 0; m < M; ++m) {
            float x = xbuf[cur][m];
            xx[m]   = pk(x, x);
            oo[m]   = pk(o[m], o[m]);
            accA[m] = pk(bt2, 0.0f);
            accB[m] = pk(0.0f, 0.0f);
        }

        #pragma unroll
        for (int q = 0; q < 5; ++q) {
            ulonglong2 wa = wbuf[cur][q];       // W1 row0, hidden 4q..4q+3
            ulonglong2 wb = wbuf[cur][5 + q];   // W1 row1
            ulonglong2 bb = b1t[q];             // b1
            ulonglong2 w2 = w2t[q];             // W2

            #pragma unroll
            for (int m = 0; m < M; ++m) {
                ull hA = fma2(xx[m], wa.x, fma2(oo[m], wb.x, bb.x));
                ull hB = fma2(xx[m], wa.y, fma2(oo[m], wb.y, bb.y));
                accA[m] = fma2(relu2(hA), w2.x, accA[m]);
                accB[m] = fma2(relu2(hB), w2.y, accB[m]);
            }
        }

        #pragma unroll
        for (int m = 0; m < M; ++m) {
            float a, b;
            upk(a, b, add2(accA[m], accB[m]));
            o[m] = fast_tanh(a + b);
            io[m][t] = o[m];            // overwrite consumed x slot with output
        }
    }

    __syncthreads();

    // ---- writeback (coalesced float4) ----
    {
        const float4* s = (const float4*)sIO;
        #pragma unroll
        for (int r = 0; r < M; ++r) {
            float4* d = (float4*)(gout + (size_t)(ebase + r * QUARTER) * TT);
            for (int i = tid; i < REGF / 4; i += THREADS) d[i] = s[r * (REGF / 4) + i];
        }
    }
}

extern "C" void kernel_launch(void* const* d_in, const int* in_sizes, int n_in,
                              void* d_out, int out_size)
{
    const float* x  = (const float*)d_in[0];
    const float* W1 = (const float*)d_in[1];

    // Populate constant bank (graph-capturable D2D memcpys, no allocation).
    void *pB1, *pW2, *pB2;
    cudaGetSymbolAddress(&pB1, cB1);
    cudaGetSymbolAddress(&pW2, cW2);
    cudaGetSymbolAddress(&pB2, cB2);
    cudaMemcpyAsync(pB1, d_in[2], sizeof(float) * TT * 20, cudaMemcpyDeviceToDevice);
    cudaMemcpyAsync(pW2, d_in[3], sizeof(float) * TT * 20, cudaMemcpyDeviceToDevice);
    cudaMemcpyAsync(pB2, d_in[4], sizeof(float) * TT,      cudaMemcpyDeviceToDevice);

    const int smem_bytes = SMEM_FLOATS * (int)sizeof(float);  // 66240
    cudaFuncSetAttribute(rnn_kernel, cudaFuncAttributeMaxDynamicSharedMemorySize, smem_bytes);

    rnn_kernel<<<BB / (M * THREADS), THREADS, smem_bytes>>>(x, W1, (float*)d_out);
}

// round 9
// speedup vs baseline: 1.0030x; 1.0030x over previous
#include <cuda_runtime.h>

typedef unsigned long long ull;

#define TT       30
#define BB       1048576
#define THREADS  256
#define HALF     (BB / 2)
#define CH       10                  // timesteps resident per phase
#define NPH      (TT / CH)           // 3 phases
#define REGF     (THREADS * CH)      // 2560 floats per region per phase

// Small weights in constant (LDC port); W1 in shared (LDS port).
__constant__ __align__(16) float cB1[TT * 20];      // 600 floats
__constant__ __align__(16) float cW2[TT * 20];      // 600
__constant__ __align__(16) float cB2[TT];           // 30

// ---------------- packed f32x2 helpers ----------------
__device__ __forceinline__ ull pk(float lo, float hi) {
    ull r; asm("mov.b64 %0, {%1,%2};" : "=l"(r) : "f"(lo), "f"(hi)); return r;
}
__device__ __forceinline__ void upk(float& lo, float& hi, ull v) {
    asm("mov.b64 {%0,%1}, %2;" : "=f"(lo), "=f"(hi) : "l"(v));
}
__device__ __forceinline__ ull fma2(ull a, ull b, ull c) {
    ull d; asm("fma.rn.f32x2 %0, %1, %2, %3;" : "=l"(d) : "l"(a), "l"(b), "l"(c)); return d;
}
__device__ __forceinline__ ull add2(ull a, ull b) {
    ull d; asm("add.rn.f32x2 %0, %1, %2;" : "=l"(d) : "l"(a), "l"(b)); return d;
}
__device__ __forceinline__ ull relu2(ull v) {
    float a, b; upk(a, b, v);
    return pk(fmaxf(a, 0.0f), fmaxf(b, 0.0f));
}
// tanh(z) = 1 - 2/(exp(2z)+1) via MUFU.EX2 + MUFU.RCP (~1e-6 rel err)
__device__ __forceinline__ float fast_tanh(float z) {
    float e; asm("ex2.approx.f32 %0, %1;" : "=f"(e) : "f"(z * 2.8853900817779268f));
    float r; asm("rcp.approx.f32 %0, %1;" : "=f"(r) : "f"(e + 1.0f));
    return fmaf(-2.0f, r, 1.0f);
}

// Shared: sW1[1200] + sIO[2 regions x 256 elems x CH] = 6320 floats = 25280 B -> 5 CTAs/SM
#define SMEM_FLOATS (1200 + 2 * REGF)

__global__ __launch_bounds__(THREADS, 5)
void rnn_kernel(const float* __restrict__ gx,
                const float* __restrict__ gW1,
                float* __restrict__ gout)
{
    __shared__ float smem[SMEM_FLOATS];
    float* sW1 = smem;
    float* sIO = smem + 1200;

    const int tid = threadIdx.x;
    const int base0 = blockIdx.x * THREADS;   // region-0 element base
    const int base1 = base0 + HALF;           // region-1 element base

    // ---- stage W1 (coalesced float4, 300 float4s, properly bounded) ----
    {
        float4*       d = (float4*)sW1;
        const float4* s = (const float4*)gW1;
        for (int i = tid; i < 300; i += THREADS) d[i] = s[i];
    }
    // ---- stage phase-0 x: fully unrolled independent loads (high MLP) ----
    #pragma unroll
    for (int k = 0; k < CH; ++k) {
        int i = tid + k * THREADS;
        int e = i / CH, j = i - e * CH;
        sIO[i]        = gx[(size_t)(base0 + e) * TT + j];
        sIO[REGF + i] = gx[(size_t)(base1 + e) * TT + j];
    }
    __syncthreads();

    float* io0 = sIO + tid * CH;
    float* io1 = sIO + REGF + tid * CH;

    const ull* w1u = (const ull*)sW1;
    const ull* b1u = (const ull*)cB1;
    const ull* w2u = (const ull*)cW2;

    float o0 = 0.0f, o1 = 0.0f;

    #pragma unroll 1
    for (int p = 0; p < NPH; ++p) {
        // ---- compute CH timesteps (R4-validated core) ----
        #pragma unroll 1
        for (int jj = 0; jj < CH; ++jj) {
            const int t = p * CH + jj;
            const ulonglong2* w1t = (const ulonglong2*)(w1u + t * 20);  // LDS.128
            const ulonglong2* b1t = (const ulonglong2*)(b1u + t * 10);  // LDC.128
            const ulonglong2* w2t = (const ulonglong2*)(w2u + t * 10);  // LDC.128
            const float bt2 = cB2[t];
            const float x0  = io0[jj];
            const float x1  = io1[jj];

            ull xx0 = pk(x0, x0), oo0 = pk(o0, o0);
            ull xx1 = pk(x1, x1), oo1 = pk(o1, o1);
            ull accA0 = pk(bt2, 0.0f), accB0 = pk(0.0f, 0.0f);
            ull accA1 = accA0,         accB1 = accB0;

            #pragma unroll
            for (int q = 0; q < 5; ++q) {
                ulonglong2 wa = w1t[q];
                ulonglong2 wb = w1t[5 + q];
                ulonglong2 bb = b1t[q];
                ulonglong2 w2 = w2t[q];

                ull hA0 = fma2(xx0, wa.x, fma2(oo0, wb.x, bb.x));
                ull hB0 = fma2(xx0, wa.y, fma2(oo0, wb.y, bb.y));
                ull hA1 = fma2(xx1, wa.x, fma2(oo1, wb.x, bb.x));
                ull hB1 = fma2(xx1, wa.y, fma2(oo1, wb.y, bb.y));

                accA0 = fma2(relu2(hA0), w2.x, accA0);
                accB0 = fma2(relu2(hB0), w2.y, accB0);
                accA1 = fma2(relu2(hA1), w2.x, accA1);
                accB1 = fma2(relu2(hB1), w2.y, accB1);
            }
            {
                float a, b;
                upk(a, b, add2(accA0, accB0));
                o0 = fast_tanh(a + b);
                upk(a, b, add2(accA1, accB1));
                o1 = fast_tanh(a + b);
            }
            io0[jj] = o0;
            io1[jj] = o1;
        }
        __syncthreads();

        // ---- writeback outputs + restage next phase's x ----
        // Fully unrolled: up to 20 independent LDG in flight; same thread owns
        // each smem slot for read-then-write -> no cross-thread hazard.
        if (p < NPH - 1) {
            #pragma unroll
            for (int k = 0; k < CH; ++k) {
                int i = tid + k * THREADS;
                int e = i / CH, j = i - e * CH;
                size_t g0 = (size_t)(base0 + e) * TT + p * CH + j;
                size_t g1 = (size_t)(base1 + e) * TT + p * CH + j;
                float v0 = sIO[i], v1 = sIO[REGF + i];
                float n0 = gx[g0 + CH], n1 = gx[g1 + CH];
                gout[g0] = v0;
                gout[g1] = v1;
                sIO[i]        = n0;
                sIO[REGF + i] = n1;
            }
        } else {
            #pragma unroll
            for (int k = 0; k < CH; ++k) {
                int i = tid + k * THREADS;
                int e = i / CH, j = i - e * CH;
                size_t g0 = (size_t)(base0 + e) * TT + p * CH + j;
                size_t g1 = (size_t)(base1 + e) * TT + p * CH + j;
                gout[g0] = sIO[i];
                gout[g1] = sIO[REGF + i];
            }
        }
        __syncthreads();
    }
}

extern "C" void kernel_launch(void* const* d_in, const int* in_sizes, int n_in,
                              void* d_out, int out_size)
{
    const float* x  = (const float*)d_in[0];
    const float* W1 = (const float*)d_in[1];

    // Populate constant bank (graph-capturable D2D memcpys, no allocation).
    void *pB1, *pW2, *pB2;
    cudaGetSymbolAddress(&pB1, cB1);
    cudaGetSymbolAddress(&pW2, cW2);
    cudaGetSymbolAddress(&pB2, cB2);
    cudaMemcpyAsync(pB1, d_in[2], sizeof(float) * TT * 20, cudaMemcpyDeviceToDevice);
    cudaMemcpyAsync(pW2, d_in[3], sizeof(float) * TT * 20, cudaMemcpyDeviceToDevice);
    cudaMemcpyAsync(pB2, d_in[4], sizeof(float) * TT,      cudaMemcpyDeviceToDevice);

    rnn_kernel<<<BB / (2 * THREADS), THREADS>>>(x, W1, (float*)d_out);
}